// round 16
// baseline (speedup 1.0000x reference)
#include <cuda_runtime.h>
#include <math.h>

#define NB 2
#define NSEG 64
#define HIMG 336
#define HP 24
#define CD 768
#define CM 3072
#define RH 48
#define HID 128
#define P2 2304
#define LNEPS 1e-12f

typedef unsigned long long ull;
typedef unsigned int uint;
#define FFMA2(acc, a, b) asm("fma.rn.f32x2 %0, %1, %2, %0;" : "+l"(acc) : "l"(a), "l"(b))
#define UNPK(lo, hi, s) asm("mov.b64 {%0,%1}, %2;" : "=f"(lo), "=f"(hi) : "l"(s))
#define BF2(u, lo, hi) \
    asm("cvt.rn.satfinite.bf16x2.f32 %0, %1, %2;" : "=r"(u) : "f"(hi), "f"(lo))
#define MMA16(c, a, b0, b1)                                                  \
    asm volatile(                                                            \
        "mma.sync.aligned.m16n8k16.row.col.f32.bf16.bf16.f32 "               \
        "{%0,%1,%2,%3},{%4,%5,%6,%7},{%8,%9},{%0,%1,%2,%3};"                 \
        : "+f"((c)[0]), "+f"((c)[1]), "+f"((c)[2]), "+f"((c)[3])             \
        : "r"((a).x), "r"((a).y), "r"((a).z), "r"((a).w), "r"(b0), "r"(b1))

__device__ float g_means[NB * NSEG * CD];
__device__ float g_wseg[(size_t)NB * NSEG * P2];
__device__ float g_wm[(size_t)6 * HID * NSEG * 9];
__device__ float g_wmp[(size_t)36 * HID * NSEG * 9];   // per-chunk partials
__device__ float g_h[(size_t)3 * NB * HID * P2];
__device__ float g_red[(size_t)NB * 96 * 8 * P2];
__device__ float g_wbf[8 * HID * 9];
__device__ float g_cb0[8];
__device__ float g_bpart[4 * NB * 8 * P2];
__device__ float g_sgp[4 * NB * 24 * P2];
__device__ float g_sbp[4 * NB * 24 * P2];
__device__ float g_x1[NB * 8 * P2];
__device__ float g_act1[NB * 8 * P2];
__device__ float g_x2[NB * 16 * P2];
__device__ float g_act2[NB * 16 * P2];
__device__ float g_stats[12];

__global__ void zero_k() {
    int i = blockIdx.x * 256 + threadIdx.x;
    if (i < 12) g_stats[i] = 0.f;
    if (i < 8 * HID * 9) g_wbf[i] = 0.f;
}

// ---------------- per-segment channel means -------------------------------
__global__ void seg_means_k(const float* __restrict__ f_sem,
                            const int* __restrict__ segmap) {
    const int s = blockIdx.x, b = blockIdx.y;
    __shared__ int segs[HP * HP];
    for (int p = threadIdx.x; p < HP * HP; p += 256) {
        int i = p / HP, j = p % HP;
        int v = segmap[((size_t)b * HIMG + i * 14) * HIMG + j * 14];
        segs[p] = min(max(v, 0), NSEG - 1);
    }
    __syncthreads();
    float acc[3] = {0.f, 0.f, 0.f};
    int cnt = 0;
    for (int p = 0; p < HP * HP; p++) {
        if (segs[p] == s) {
            cnt++;
            int i = p / HP, j = p % HP;
#pragma unroll
            for (int k = 0; k < 3; k++) {
                int c = threadIdx.x + k * 256;
                acc[k] += f_sem[(((size_t)b * CD + c) * HP + i) * HP + j];
            }
        }
    }
    float inv = cnt > 0 ? 1.0f / (float)cnt : 0.0f;
#pragma unroll
    for (int k = 0; k < 3; k++) {
        int c = threadIdx.x + k * 256;
        g_means[((size_t)b * NSEG + s) * CD + c] = acc[k] * inv;
    }
}

// -------- antialiased bilinear 336->48 weights per segment ------------------
__global__ void paint_wseg_k(const int* __restrict__ segmap) {
    const int X = blockIdx.x, Y = blockIdx.y, b = blockIdx.z;
    const int t = threadIdx.x;
    __shared__ float wseg[NSEG];
    __shared__ float wy[15], wx[15];

    if (t < NSEG) wseg[t] = 0.f;
    if (t == 0) {
        float sf = 7.0f * Y + 3.0f, norm = 0.f;
        for (int k = 0; k < 15; k++) {
            int y = 7 * Y - 4 + k;
            float w = (y >= 0 && y < HIMG)
                          ? fmaxf(0.f, 1.f - fabsf((float)y - sf) * (1.f / 7.f)) : 0.f;
            wy[k] = w; norm += w;
        }
        float inv = 1.f / norm;
        for (int k = 0; k < 15; k++) wy[k] *= inv;
    }
    if (t == 1) {
        float sf = 7.0f * X + 3.0f, norm = 0.f;
        for (int k = 0; k < 15; k++) {
            int x = 7 * X - 4 + k;
            float w = (x >= 0 && x < HIMG)
                          ? fmaxf(0.f, 1.f - fabsf((float)x - sf) * (1.f / 7.f)) : 0.f;
            wx[k] = w; norm += w;
        }
        float inv = 1.f / norm;
        for (int k = 0; k < 15; k++) wx[k] *= inv;
    }
    __syncthreads();

    if (t < 225) {
        int ty = t / 15, tx = t % 15;
        int y = 7 * Y - 4 + ty, x = 7 * X - 4 + tx;
        if (y >= 0 && y < HIMG && x >= 0 && x < HIMG) {
            float w = wy[ty] * wx[tx];
            if (w != 0.f) {
                int seg = segmap[((size_t)b * HIMG + y) * HIMG + x];
                seg = min(max(seg, 0), NSEG - 1);
                atomicAdd(&wseg[seg], w);
            }
        }
    }
    __syncthreads();
    if (t < NSEG)
        g_wseg[((size_t)b * NSEG + t) * P2 + Y * RH + X] = wseg[t];
}

// -------- fold means into shconv weights: register-tiled partials -----------
// grid (6 zz, 4 co-groups of 32, 6 K-chunks of 128), 256 threads.
// Warp = 32 couts (lanes); thread tile = 9 taps x 8 s values.
__global__ void __launch_bounds__(256) fold_wm_part_k(
    const float* __restrict__ ws0, const float* __restrict__ ws1,
    const float* __restrict__ ws2) {
    __shared__ float msm[NSEG * 128];       // 32 KB
    __shared__ float wsm[16 * 9 * 33];      // 19 KB
    const int zz = blockIdx.x, layer = zz >> 1, b = zz & 1;
    const int co0 = blockIdx.y * 32;
    const int chunk = blockIdx.z, ci0 = chunk * 128;
    const float* ws = layer == 0 ? ws0 : (layer == 1 ? ws1 : ws2);
    const int t = threadIdx.x, w = t >> 5, lane = t & 31;
    const int sw = w * 8;

    float acc[9][8];
#pragma unroll
    for (int tap = 0; tap < 9; tap++)
#pragma unroll
        for (int i = 0; i < 8; i++) acc[tap][i] = 0.f;

    for (int i = t; i < NSEG * 128; i += 256) {
        int ss = i >> 7, cc = i & 127;
        msm[i] = g_means[((size_t)b * NSEG + ss) * CD + ci0 + cc];
    }

    for (int sub = 0; sub < 8; sub++) {
        __syncthreads();
        for (int i = t; i < 16 * 9 * 32; i += 256) {
            int co = i / 144, rem = i - co * 144;
            int cc = rem / 9, tap = rem - cc * 9;
            wsm[(cc * 9 + tap) * 33 + co] =
                ws[((size_t)(co0 + co) * CD + ci0 + sub * 16 + cc) * 9 + tap];
        }
        __syncthreads();
#pragma unroll 4
        for (int cc = 0; cc < 16; cc++) {
            float m[8];
            const float* mp = msm + sub * 16 + cc;
#pragma unroll
            for (int i = 0; i < 8; i++) m[i] = mp[(sw + i) * 128];
#pragma unroll
            for (int tap = 0; tap < 9; tap++) {
                float wv = wsm[(cc * 9 + tap) * 33 + lane];
#pragma unroll
                for (int i = 0; i < 8; i++)
                    acc[tap][i] = fmaf(wv, m[i], acc[tap][i]);
            }
        }
    }
    float* op = g_wmp + ((size_t)(chunk * 6 + zz) * HID + co0 + lane) * 576;
#pragma unroll
    for (int tap = 0; tap < 9; tap++)
#pragma unroll
        for (int i = 0; i < 8; i++)
            op[(sw + i) * 9 + tap] = acc[tap][i];
}

// reduce 6 K-chunk partials -> g_wm
__global__ void wm_reduce_k() {
    const int idx = blockIdx.x * 256 + threadIdx.x;   // over 6*HID*576
    if (idx >= 6 * HID * 576) return;
    const int zz = idx / (HID * 576);
    const int rem = idx - zz * (HID * 576);
    float s = 0.f;
#pragma unroll
    for (int c = 0; c < 6; c++)
        s += g_wmp[(size_t)(c * 6 + zz) * (HID * 576) + rem];
    g_wm[idx] = s;
}

// ---------------- layernorm stats, float4 ----------------------------------
__global__ void ln_stats4_k(const float4* __restrict__ x, int n4PerB, int layer) {
    const int b = blockIdx.y;
    const float4* xb = x + (size_t)b * n4PerB;
    float s = 0.f, s2 = 0.f;
    for (int i = blockIdx.x * blockDim.x + threadIdx.x; i < n4PerB;
         i += gridDim.x * blockDim.x) {
        float4 v = xb[i];
        s += (v.x + v.y) + (v.z + v.w);
        s2 = fmaf(v.x, v.x, fmaf(v.y, v.y, fmaf(v.z, v.z, fmaf(v.w, v.w, s2))));
    }
#pragma unroll
    for (int o = 16; o; o >>= 1) {
        s += __shfl_down_sync(0xffffffffu, s, o);
        s2 += __shfl_down_sync(0xffffffffu, s2, o);
    }
    __shared__ float sh[32][2];
    int w = threadIdx.x >> 5, l = threadIdx.x & 31;
    if (l == 0) { sh[w][0] = s; sh[w][1] = s2; }
    __syncthreads();
    if (threadIdx.x < 32) {
        int nw = blockDim.x >> 5;
        s = (threadIdx.x < nw) ? sh[threadIdx.x][0] : 0.f;
        s2 = (threadIdx.x < nw) ? sh[threadIdx.x][1] : 0.f;
#pragma unroll
        for (int o = 16; o; o >>= 1) {
            s += __shfl_down_sync(0xffffffffu, s, o);
            s2 += __shfl_down_sync(0xffffffffu, s2, o);
        }
        if (threadIdx.x == 0) {
            atomicAdd(&g_stats[layer * 4 + b * 2 + 0], s);
            atomicAdd(&g_stats[layer * 4 + b * 2 + 1], s2);
        }
    }
}

// ---- staging helpers -------------------------------------------------------
template <int CI, int NE>
__device__ __forceinline__ void stage_pre(int* gofs, int* sofs,
                                          int ty0, int tx0, int t) {
#pragma unroll
    for (int k = 0; k < NE; k++) {
        int idx = t + k * 128;
        if (idx < CI * 324) {
            int ci = idx / 324, q = idx - ci * 324;
            int row = q / 18, col = q - row * 18;
            int y = ty0 + row - 1, x = tx0 + col - 1;
            bool vin = (unsigned)y < RH && (unsigned)x < RH;
            gofs[k] = vin ? (ci * P2 + y * RH + x) : -1;
            sofs[k] = (ci * 18 + row) * 20 + col;
        } else {
            gofs[k] = -1;
            sofs[k] = 18;
        }
    }
}

template <int CI, int NE>
__device__ __forceinline__ void stage_run(float* scp, const float* __restrict__ icb,
                                          const int* gofs, const int* sofs) {
#pragma unroll
    for (int k = 0; k < NE; k++) {
        int go = gofs[k];
        float v = (go >= 0) ? __ldg(icb + go) : 0.f;
        scp[sofs[k]] = v;
        scp[sofs[k] + (CI * 360 - 1)] = v;
        scp[sofs[k] + (2 * CI * 360 - 2)] = v;
    }
}

// ------- shared conv over 64 segment-channels + bias + relu -> g_h ----------
#define SCI 4
#define SNE 11
__global__ void __launch_bounds__(128) shconv_k(
    const float* __restrict__ bs0, const float* __restrict__ bs1,
    const float* __restrict__ bs2) {
    __shared__ __align__(16) float scp[3 * SCI * 360];
    __shared__ __align__(16) float2 wdup[SCI * 9 * 32];
    const int tile = blockIdx.x;
    const int ty0 = (tile / 3) * 16, tx0 = (tile % 3) * 16;
    const int co0 = blockIdx.y * 32;
    const int zz = blockIdx.z, layer = zz >> 1, b = zz & 1;
    const float* bias = layer == 0 ? bs0 : (layer == 1 ? bs1 : bs2);
    const float* wt = g_wm + (size_t)zz * HID * NSEG * 9;
    const float* in = g_wseg + (size_t)b * NSEG * P2;
    float* outp = g_h + (size_t)zz * HID * P2;
    const int t = threadIdx.x;
    const int co_i = t & 3, g = t >> 2, r = g >> 1, hh = g & 1;

    int gofs[SNE], sofs[SNE];
    stage_pre<SCI, SNE>(gofs, sofs, ty0, tx0, t);

    ull acc[8][4];
#pragma unroll
    for (int j = 0; j < 8; j++)
#pragma unroll
        for (int i = 0; i < 4; i++) acc[j][i] = 0ULL;

    for (int cb = 0; cb < NSEG; cb += SCI) {
        __syncthreads();
        stage_run<SCI, SNE>(scp, in + (size_t)cb * P2, gofs, sofs);
        for (int idx = t; idx < 32 * SCI * 9; idx += 128) {
            int co_l = idx / (SCI * 9), rem = idx - co_l * (SCI * 9);
            int ci = rem / 9, tap = rem - ci * 9;
            float w = wt[((size_t)(co0 + co_l) * NSEG + cb + ci) * 9 + tap];
            wdup[(ci * 9 + tap) * 32 + co_l] = make_float2(w, w);
        }
        __syncthreads();
#pragma unroll
        for (int ci = 0; ci < SCI; ci++) {
#pragma unroll
            for (int ky = 0; ky < 3; ky++) {
#pragma unroll
                for (int kx = 0; kx < 3; kx++) {
                    const ulonglong2* pp = (const ulonglong2*)(scp + kx * (SCI * 360) +
                        (ci * 18 + r + ky) * 20 + hh * 8);
                    ulonglong2 pA = pp[0], pB = pp[1];
                    const ulonglong2* wp = (const ulonglong2*)(wdup +
                        (ci * 9 + ky * 3 + kx) * 32 + co_i * 8);
                    ulonglong2 wA = wp[0], wB = wp[1], wC = wp[2], wD = wp[3];
                    FFMA2(acc[0][0], pA.x, wA.x); FFMA2(acc[0][1], pA.y, wA.x);
                    FFMA2(acc[0][2], pB.x, wA.x); FFMA2(acc[0][3], pB.y, wA.x);
                    FFMA2(acc[1][0], pA.x, wA.y); FFMA2(acc[1][1], pA.y, wA.y);
                    FFMA2(acc[1][2], pB.x, wA.y); FFMA2(acc[1][3], pB.y, wA.y);
                    FFMA2(acc[2][0], pA.x, wB.x); FFMA2(acc[2][1], pA.y, wB.x);
                    FFMA2(acc[2][2], pB.x, wB.x); FFMA2(acc[2][3], pB.y, wB.x);
                    FFMA2(acc[3][0], pA.x, wB.y); FFMA2(acc[3][1], pA.y, wB.y);
                    FFMA2(acc[3][2], pB.x, wB.y); FFMA2(acc[3][3], pB.y, wB.y);
                    FFMA2(acc[4][0], pA.x, wC.x); FFMA2(acc[4][1], pA.y, wC.x);
                    FFMA2(acc[4][2], pB.x, wC.x); FFMA2(acc[4][3], pB.y, wC.x);
                    FFMA2(acc[5][0], pA.x, wC.y); FFMA2(acc[5][1], pA.y, wC.y);
                    FFMA2(acc[5][2], pB.x, wC.y); FFMA2(acc[5][3], pB.y, wC.y);
                    FFMA2(acc[6][0], pA.x, wD.x); FFMA2(acc[6][1], pA.y, wD.x);
                    FFMA2(acc[6][2], pB.x, wD.x); FFMA2(acc[6][3], pB.y, wD.x);
                    FFMA2(acc[7][0], pA.x, wD.y); FFMA2(acc[7][1], pA.y, wD.y);
                    FFMA2(acc[7][2], pB.x, wD.y); FFMA2(acc[7][3], pB.y, wD.y);
                }
            }
        }
    }
    const int pg = (ty0 + r) * RH + tx0 + hh * 8;
#pragma unroll
    for (int j = 0; j < 8; j++) {
        int c = co0 + co_i * 8 + j;
        float bv = bias[c];
        float f[8];
#pragma unroll
        for (int i = 0; i < 4; i++) UNPK(f[2 * i], f[2 * i + 1], acc[j][i]);
        *(float4*)(outp + (size_t)c * P2 + pg) =
            make_float4(fmaxf(f[0] + bv, 0.f), fmaxf(f[1] + bv, 0.f),
                        fmaxf(f[2] + bv, 0.f), fmaxf(f[3] + bv, 0.f));
        *(float4*)(outp + (size_t)c * P2 + pg + 4) =
            make_float4(fmaxf(f[4] + bv, 0.f), fmaxf(f[5] + bv, 0.f),
                        fmaxf(f[6] + bv, 0.f), fmaxf(f[7] + bv, 0.f));
    }
}

// ------- fold beta weights --------------------------------------------------
__global__ void fold_wb_k(const float* __restrict__ w0, const float* __restrict__ wb) {
    const int k = blockIdx.x * 128 + threadIdx.x;
    const int c0 = blockIdx.y * 128;
    __shared__ float w0s[8][128];
    for (int i = threadIdx.x; i < 8 * 128; i += 128)
        w0s[i >> 7][i & 127] = w0[(size_t)(i >> 7) * CM + c0 + (i & 127)];
    __syncthreads();
    float acc[8] = {0, 0, 0, 0, 0, 0, 0, 0};
#pragma unroll 4
    for (int cc = 0; cc < 128; cc++) {
        float v = wb[(size_t)(c0 + cc) * (HID * 9) + k];
#pragma unroll
        for (int j = 0; j < 8; j++) acc[j] = fmaf(w0s[j][cc], v, acc[j]);
    }
#pragma unroll
    for (int j = 0; j < 8; j++) atomicAdd(&g_wbf[j * (HID * 9) + k], acc[j]);
}

__global__ void cb0_k(const float* __restrict__ w0, const float* __restrict__ bb) {
    const int j = blockIdx.x;
    float s = 0.f;
    for (int c = threadIdx.x; c < CM; c += 256)
        s = fmaf(w0[(size_t)j * CM + c], bb[c], s);
#pragma unroll
    for (int o = 16; o; o >>= 1) s += __shfl_down_sync(~0u, s, o);
    __shared__ float sh[8];
    if ((threadIdx.x & 31) == 0) sh[threadIdx.x >> 5] = s;
    __syncthreads();
    if (threadIdx.x == 0) {
        float r = 0.f;
        for (int w = 0; w < 8; w++) r += sh[w];
        g_cb0[j] = r;
    }
}

// ------- beta conv (channel-split x4): 32ci of h -> 8ch partials ------------
__global__ void conv_beta_k() {
    const int tile = blockIdx.x, sp = blockIdx.y, b = blockIdx.z;
    const int ty0 = (tile / 3) * 16, tx0 = (tile % 3) * 16;
    const int t = threadIdx.x;
    const int py = t >> 4, px = t & 15;
    __shared__ float sin_s[8][324];
    __shared__ float sw[8][8][9];
    float acc[8] = {0, 0, 0, 0, 0, 0, 0, 0};
    const float* hin = g_h + (size_t)b * HID * P2;
    for (int cb = sp * 32; cb < sp * 32 + 32; cb += 8) {
        for (int idx = t; idx < 8 * 324; idx += 256) {
            int c = idx / 324, q = idx - c * 324;
            int iy = ty0 + q / 18 - 1, ix = tx0 + (q % 18) - 1;
            float v = 0.f;
            if ((unsigned)iy < RH && (unsigned)ix < RH)
                v = hin[(size_t)(cb + c) * P2 + iy * RH + ix];
            sin_s[c][q] = v;
        }
        for (int idx = t; idx < 576; idx += 256) {
            int co = idx / 72, rr = idx - co * 72;
            sw[co][rr / 9][rr % 9] = g_wbf[co * (HID * 9) + (cb + rr / 9) * 9 + (rr % 9)];
        }
        __syncthreads();
#pragma unroll
        for (int ci = 0; ci < 8; ci++) {
            float v[9];
#pragma unroll
            for (int ky = 0; ky < 3; ky++)
#pragma unroll
                for (int kx = 0; kx < 3; kx++)
                    v[ky * 3 + kx] = sin_s[ci][(py + ky) * 18 + px + kx];
#pragma unroll
            for (int co = 0; co < 8; co++) {
                float a = acc[co];
#pragma unroll
                for (int k = 0; k < 9; k++) a = fmaf(v[k], sw[co][ci][k], a);
                acc[co] = a;
            }
        }
        __syncthreads();
    }
    const int p = (ty0 + py) * RH + tx0 + px;
#pragma unroll
    for (int co = 0; co < 8; co++)
        g_bpart[((sp * NB + b) * 8 + co) * P2 + p] = acc[co];
}

// ------- layer0: bf16 mma gamma conv + fused LN + 1x1 contraction -----------
__global__ void __launch_bounds__(128) spade0_k(
    const float* __restrict__ wg, const float* __restrict__ bg,
    const float* __restrict__ x, const float* __restrict__ w0) {
    __shared__ uint ppatch[8 * 360];
    __shared__ uint afrag[9 * 2 * 32 * 4];
    __shared__ float w0s[8][32], w0ps[8][32];

    const int tile = blockIdx.x;
    const int ty0 = (tile / 3) * 16, tx0 = (tile % 3) * 16;
    const int co0 = blockIdx.y * 32;
    const int b = blockIdx.z;
    const float* hin = g_h + (size_t)b * HID * P2;
    const int t = threadIdx.x;
    const int wid = t >> 5, l = t & 31, g4 = l >> 2, k4 = l & 3;

    for (int i = t; i < 256; i += 128) {
        int j8 = i >> 5, col = i & 31;
        float wv = w0[(size_t)j8 * CM + co0 + col];
        w0s[j8][col] = wv;
        w0ps[j8][col] = wv * (1.f + bg[co0 + col]);
    }

    float acc[2][8][4];
#pragma unroll
    for (int m = 0; m < 2; m++)
#pragma unroll
        for (int n = 0; n < 8; n++)
#pragma unroll
            for (int i = 0; i < 4; i++) acc[m][n][i] = 0.f;

    for (int cb = 0; cb < HID; cb += 16) {
        __syncthreads();
        for (int i = t; i < 8 * 324; i += 128) {
            int p = i / 324, q = i - p * 324;
            int ry = q / 18, rx = q - ry * 18;
            int y = ty0 + ry - 1, xx = tx0 + rx - 1;
            float v0 = 0.f, v1 = 0.f;
            if ((unsigned)y < RH && (unsigned)xx < RH) {
                size_t o = (size_t)(cb + 2 * p) * P2 + y * RH + xx;
                v0 = __ldg(hin + o);
                v1 = __ldg(hin + o + P2);
            }
            uint u; BF2(u, v0, v1);
            ppatch[p * 360 + ry * 20 + rx] = u;
        }
        for (int i = t; i < 32 * 8 * 9; i += 128) {
            int co = i / 72, rem = i - co * 72;
            int p = rem / 9, tap = rem - p * 9;
            size_t base = ((size_t)(co0 + co) * HID + cb + 2 * p) * 9 + tap;
            float v0 = wg[base], v1 = wg[base + 9];
            uint u; BF2(u, v0, v1);
            int m = co >> 4, row = co & 15;
            int lane_a = (row & 7) * 4 + (p & 3);
            int reg = (row >> 3) + 2 * (p >> 2);
            afrag[((tap * 2 + m) * 32 + lane_a) * 4 + reg] = u;
        }
        __syncthreads();
#pragma unroll
        for (int tap = 0; tap < 9; tap++) {
            const int ky = tap / 3, kx = tap - ky * 3;
            uint4 am0 = *(const uint4*)&afrag[((tap * 2 + 0) * 32 + l) * 4];
            uint4 am1 = *(const uint4*)&afrag[((tap * 2 + 1) * 32 + l) * 4];
            const uint* pb = ppatch + k4 * 360 + ky * 20 + kx;
#pragma unroll
            for (int n8 = 0; n8 < 8; n8++) {
                int y = wid * 4 + (n8 >> 1);
                int xx = (n8 & 1) * 8 + g4;
                uint b0 = pb[y * 20 + xx];
                uint b1 = pb[y * 20 + xx + 4 * 360];
                MMA16(acc[0][n8], am0, b0, b1);
                MMA16(acc[1][n8], am1, b0, b1);
            }
        }
    }

    const float sum = g_stats[b * 2 + 0], sumsq = g_stats[b * 2 + 1];
    const float invN = 1.f / ((float)CM * P2);
    const float mean = sum * invN;
    const float rstd = rsqrtf(sumsq * invN - mean * mean + LNEPS);

    float* rp = g_red + ((size_t)(b * 96 + blockIdx.y) * 8) * P2;
#pragma unroll
    for (int n8 = 0; n8 < 8; n8++) {
        const int y = wid * 4 + (n8 >> 1);
        const int xc = (n8 & 1) * 8 + k4 * 2;
        const int pix = (ty0 + y) * RH + tx0 + xc;
        float s0[8], s1[8];
#pragma unroll
        for (int j = 0; j < 8; j++) { s0[j] = 0.f; s1[j] = 0.f; }
#pragma unroll
        for (int m = 0; m < 2; m++) {
#pragma unroll
            for (int rh = 0; rh < 2; rh++) {
                int col = m * 16 + rh * 8 + g4;
                float2 xv = *(const float2*)(x + ((size_t)b * CM + co0 + col) * P2 + pix);
                float xn0 = (xv.x - mean) * rstd;
                float xn1 = (xv.y - mean) * rstd;
                float g0 = acc[m][n8][rh * 2 + 0];
                float g1 = acc[m][n8][rh * 2 + 1];
                float xg0 = xn0 * g0, xg1 = xn1 * g1;
#pragma unroll
                for (int j = 0; j < 8; j++) {
                    s0[j] = fmaf(xg0, w0s[j][col], fmaf(xn0, w0ps[j][col], s0[j]));
                    s1[j] = fmaf(xg1, w0s[j][col], fmaf(xn1, w0ps[j][col], s1[j]));
                }
            }
        }
#pragma unroll
        for (int j = 0; j < 8; j++) {
            float a0 = s0[j], a1 = s1[j];
            a0 += __shfl_xor_sync(~0u, a0, 4);
            a0 += __shfl_xor_sync(~0u, a0, 8);
            a0 += __shfl_xor_sync(~0u, a0, 16);
            a1 += __shfl_xor_sync(~0u, a1, 4);
            a1 += __shfl_xor_sync(~0u, a1, 8);
            a1 += __shfl_xor_sync(~0u, a1, 16);
            if (g4 == 0) {
                rp[(size_t)j * P2 + pix] = a0;
                rp[(size_t)j * P2 + pix + 1] = a1;
            }
        }
    }
}

__device__ __forceinline__ float softplus_f(float z) {
    return fmaxf(z, 0.f) + log1pf(expf(-fabsf(z)));
}

// reduce spade0 partials + beta(4 slabs) + consts -> x1
__global__ void reduce_x1_k(const float* __restrict__ bias0) {
    const int idx = blockIdx.x * 256 + threadIdx.x;
    const int b = idx / (8 * P2);
    const int rem = idx - b * (8 * P2);
    const int j = rem / P2, p = rem - j * P2;
    const int bo = (b * 8 + j) * P2 + p;
    float s = g_cb0[j] + bias0[j];
#pragma unroll
    for (int sp = 0; sp < 4; sp++) s += g_bpart[sp * NB * 8 * P2 + bo];
    const float* base = g_red + ((size_t)b * 96 * 8 + j) * P2 + p;
#pragma unroll 8
    for (int k = 0; k < 96; k++) s += base[(size_t)k * 8 * P2];
    g_x1[idx] = softplus_f(s);
}

// ------- small spade partials (layers 1/2, channel-split x4) ----------------
__global__ void spade_part_k(const float* __restrict__ hin,
                             const float* __restrict__ wg,
                             const float* __restrict__ wb, int ch_off) {
    const int tile = blockIdx.x;
    const int ty0 = (tile / 3) * 16, tx0 = (tile % 3) * 16;
    const int co_g = blockIdx.y >> 2, sp = blockIdx.y & 3;
    const int co0 = co_g * 8;
    const int b = blockIdx.z;
    const int t = threadIdx.x;
    const int py = t >> 4, px = t & 15;

    __shared__ float sin_s[8][324];
    __shared__ float swg[8][8][9];
    __shared__ float swb[8][8][9];

    float accg[8], accb[8];
#pragma unroll
    for (int i = 0; i < 8; i++) { accg[i] = 0.f; accb[i] = 0.f; }

    const size_t inB = (size_t)b * HID * P2;
    for (int cb = sp * 32; cb < sp * 32 + 32; cb += 8) {
        for (int idx = t; idx < 8 * 324; idx += 256) {
            int c = idx / 324, q = idx - c * 324;
            int iy = ty0 + q / 18 - 1, ix = tx0 + (q % 18) - 1;
            float v = 0.f;
            if ((unsigned)iy < RH && (unsigned)ix < RH)
                v = hin[inB + (size_t)(cb + c) * P2 + iy * RH + ix];
            sin_s[c][q] = v;
        }
        for (int idx = t; idx < 576; idx += 256) {
            int co = idx / 72, rr = idx - co * 72;
            size_t wi = ((size_t)(co0 + co) * HID + cb + rr / 9) * 9 + (rr % 9);
            swg[co][rr / 9][rr % 9] = wg[wi];
            swb[co][rr / 9][rr % 9] = wb[wi];
        }
        __syncthreads();
#pragma unroll
        for (int ci = 0; ci < 8; ci++) {
            float v[9];
#pragma unroll
            for (int ky = 0; ky < 3; ky++)
#pragma unroll
                for (int kx = 0; kx < 3; kx++)
                    v[ky * 3 + kx] = sin_s[ci][(py + ky) * 18 + px + kx];
#pragma unroll
            for (int co = 0; co < 8; co++) {
                float agv = accg[co], abv = accb[co];
#pragma unroll
                for (int k = 0; k < 9; k++) {
                    agv = fmaf(v[k], swg[co][ci][k], agv);
                    abv = fmaf(v[k], swb[co][ci][k], abv);
                }
                accg[co] = agv; accb[co] = abv;
            }
        }
        __syncthreads();
    }

    const int p = (ty0 + py) * RH + tx0 + px;
#pragma unroll
    for (int co = 0; co < 8; co++) {
        int ch = ch_off + co0 + co;
        g_sgp[((sp * NB + b) * 24 + ch) * P2 + p] = accg[co];
        g_sbp[((sp * NB + b) * 24 + ch) * P2 + p] = accb[co];
    }
}

// merge partials + LN apply -> act
__global__ void merge_small_k(const float* __restrict__ x,
                              const float* __restrict__ bg,
                              const float* __restrict__ bb,
                              float* __restrict__ act,
                              int layer, int nf, int ch_off, float invN) {
    const int idx = blockIdx.x * 256 + threadIdx.x;
    if (idx >= NB * nf * P2) return;
    const int b = idx / (nf * P2);
    const int rem = idx - b * (nf * P2);
    const int c = rem / P2, p = rem - c * P2;
    float gv = 0.f, bv = 0.f;
#pragma unroll
    for (int sp = 0; sp < 4; sp++) {
        int o = ((sp * NB + b) * 24 + ch_off + c) * P2 + p;
        gv += g_sgp[o];
        bv += g_sbp[o];
    }
    const float sum = g_stats[layer * 4 + b * 2 + 0];
    const float sumsq = g_stats[layer * 4 + b * 2 + 1];
    const float mean = sum * invN;
    const float rstd = rsqrtf(sumsq * invN - mean * mean + LNEPS);
    float xv = x[idx];
    act[idx] = fmaf((xv - mean) * rstd, 1.f + gv + bg[c], bv + bb[c]);
}

template <int COUT>
__global__ void conv1x1_softplus_k(const float* __restrict__ act,
                                   const float* __restrict__ w,
                                   const float* __restrict__ bias,
                                   float* __restrict__ out, int Cin) {
    const int p = blockIdx.x * blockDim.x + threadIdx.x;
    const int b = blockIdx.y;
    float acc[COUT];
#pragma unroll
    for (int j = 0; j < COUT; j++) acc[j] = 0.f;
    const float* ab = act + (size_t)b * Cin * P2 + p;
#pragma unroll 4
    for (int c = 0; c < Cin; c++) {
        float v = ab[(size_t)c * P2];
#pragma unroll
        for (int j = 0; j < COUT; j++)
            acc[j] = fmaf(__ldg(&w[(size_t)j * Cin + c]), v, acc[j]);
    }
#pragma unroll
    for (int j = 0; j < COUT; j++)
        out[((size_t)b * COUT + j) * P2 + p] = softplus_f(acc[j] + bias[j]);
}

// ---------------------------------------------------------------------------
static float* sym_ptr(const void* sym) {
    void* p = nullptr;
    cudaGetSymbolAddress(&p, sym);
    return (float*)p;
}

extern "C" void kernel_launch(void* const* d_in, const int* in_sizes, int n_in,
                              void* d_out, int out_size) {
    const float* x_main = (const float*)d_in[0];
    const float* f_sem = (const float*)d_in[1];
    const int* segmap = (const int*)d_in[2];
    const float* ws[3] = {(const float*)d_in[3], (const float*)d_in[9], (const float*)d_in[15]};
    const float* bs[3] = {(const float*)d_in[4], (const float*)d_in[10], (const float*)d_in[16]};
    const float* wg[3] = {(const float*)d_in[5], (const float*)d_in[11], (const float*)d_in[17]};
    const float* bg[3] = {(const float*)d_in[6], (const float*)d_in[12], (const float*)d_in[18]};
    const float* wb[3] = {(const float*)d_in[7], (const float*)d_in[13], (const float*)d_in[19]};
    const float* bb[3] = {(const float*)d_in[8], (const float*)d_in[14], (const float*)d_in[20]};
    const float* w1x[3] = {(const float*)d_in[21], (const float*)d_in[23], (const float*)d_in[25]};
    const float* b1x[3] = {(const float*)d_in[22], (const float*)d_in[24], (const float*)d_in[26]};
    float* out = (float*)d_out;

    float* p_h = sym_ptr(g_h);
    float* p_x1 = sym_ptr(g_x1);
    float* p_act1 = sym_ptr(g_act1);
    float* p_x2 = sym_ptr(g_x2);
    float* p_act2 = sym_ptr(g_act2);

    zero_k<<<36, 256>>>();
    seg_means_k<<<dim3(NSEG, NB), 256>>>(f_sem, segmap);
    paint_wseg_k<<<dim3(RH, RH, NB), 256>>>(segmap);
    fold_wm_part_k<<<dim3(6, 4, 6), 256>>>(ws[0], ws[1], ws[2]);
    wm_reduce_k<<<(6 * HID * 576 + 255) / 256, 256>>>();
    fold_wb_k<<<dim3(9, 24), 128>>>(w1x[0], wb[0]);
    cb0_k<<<8, 256>>>(w1x[0], bb[0]);
    ln_stats4_k<<<dim3(512, NB), 256>>>((const float4*)x_main, CM * P2 / 4, 0);

    shconv_k<<<dim3(9, HID / 32, 6), 128>>>(bs[0], bs[1], bs[2]);
    conv_beta_k<<<dim3(9, 4, NB), 256>>>();

    spade_part_k<<<dim3(9, 4, NB), 256>>>(p_h + (size_t)1 * NB * HID * P2,
                                          wg[1], wb[1], 0);
    spade_part_k<<<dim3(9, 8, NB), 256>>>(p_h + (size_t)2 * NB * HID * P2,
                                          wg[2], wb[2], 8);

    // ---- layer 0 ----
    spade0_k<<<dim3(9, CM / 32, NB), 128>>>(wg[0], bg[0], x_main, w1x[0]);
    reduce_x1_k<<<(NB * 8 * P2) / 256, 256>>>(b1x[0]);

    // ---- layer 1 ----
    ln_stats4_k<<<dim3(2, NB), 256>>>((const float4*)p_x1, 8 * P2 / 4, 1);
    merge_small_k<<<(NB * 8 * P2 + 255) / 256, 256>>>(p_x1, bg[1], bb[1], p_act1,
                                                      1, 8, 0, 1.f / (8 * P2));
    conv1x1_softplus_k<16><<<dim3(9, NB), 256>>>(p_act1, w1x[1], b1x[1], p_x2, 8);

    // ---- layer 2 ----
    ln_stats4_k<<<dim3(2, NB), 256>>>((const float4*)p_x2, 16 * P2 / 4, 2);
    merge_small_k<<<(NB * 16 * P2 + 255) / 256, 256>>>(p_x2, bg[2], bb[2], p_act2,
                                                       2, 16, 8, 1.f / (16 * P2));
    conv1x1_softplus_k<1><<<dim3(9, NB), 256>>>(p_act2, w1x[2], b1x[2], out, 16);
}

// round 17
// speedup vs baseline: 1.3624x; 1.3624x over previous
#include <cuda_runtime.h>
#include <math.h>

#define NB 2
#define NSEG 64
#define HIMG 336
#define HP 24
#define CD 768
#define CM 3072
#define RH 48
#define HID 128
#define P2 2304
#define LNEPS 1e-12f

typedef unsigned long long ull;
typedef unsigned int uint;
#define FFMA2(acc, a, b) asm("fma.rn.f32x2 %0, %1, %2, %0;" : "+l"(acc) : "l"(a), "l"(b))
#define UNPK(lo, hi, s) asm("mov.b64 {%0,%1}, %2;" : "=f"(lo), "=f"(hi) : "l"(s))
#define BF2(u, lo, hi) \
    asm("cvt.rn.satfinite.bf16x2.f32 %0, %1, %2;" : "=r"(u) : "f"(hi), "f"(lo))
#define MMA16(c, a, b0, b1)                                                  \
    asm volatile(                                                            \
        "mma.sync.aligned.m16n8k16.row.col.f32.bf16.bf16.f32 "               \
        "{%0,%1,%2,%3},{%4,%5,%6,%7},{%8,%9},{%0,%1,%2,%3};"                 \
        : "+f"((c)[0]), "+f"((c)[1]), "+f"((c)[2]), "+f"((c)[3])             \
        : "r"((a).x), "r"((a).y), "r"((a).z), "r"((a).w), "r"(b0), "r"(b1))

__device__ float g_means[NB * NSEG * CD];
__device__ float g_wseg[(size_t)NB * NSEG * P2];
__device__ float g_wm[(size_t)6 * HID * NSEG * 9];
__device__ float g_wmp[(size_t)24 * HID * NSEG * 9];
__device__ float g_h[(size_t)3 * NB * HID * P2];
__device__ float g_red[(size_t)NB * 96 * 8 * P2];
__device__ float g_wbf[8 * HID * 9];
__device__ float g_cb0[8];
__device__ float g_bpart[4 * NB * 8 * P2];
__device__ float g_sgp[4 * NB * 24 * P2];
__device__ float g_sbp[4 * NB * 24 * P2];
__device__ float g_x1[NB * 8 * P2];
__device__ float g_act1[NB * 8 * P2];
__device__ float g_x2[NB * 16 * P2];
__device__ float g_act2[NB * 16 * P2];
__device__ float g_stats[12];

__global__ void zero_k() {
    int i = blockIdx.x * 256 + threadIdx.x;
    if (i < 12) g_stats[i] = 0.f;
    if (i < 8 * HID * 9) g_wbf[i] = 0.f;
}

// ---------------- per-segment channel means -------------------------------
__global__ void seg_means_k(const float* __restrict__ f_sem,
                            const int* __restrict__ segmap) {
    const int s = blockIdx.x, b = blockIdx.y;
    __shared__ int segs[HP * HP];
    for (int p = threadIdx.x; p < HP * HP; p += 256) {
        int i = p / HP, j = p % HP;
        int v = segmap[((size_t)b * HIMG + i * 14) * HIMG + j * 14];
        segs[p] = min(max(v, 0), NSEG - 1);
    }
    __syncthreads();
    float acc[3] = {0.f, 0.f, 0.f};
    int cnt = 0;
    for (int p = 0; p < HP * HP; p++) {
        if (segs[p] == s) {
            cnt++;
            int i = p / HP, j = p % HP;
#pragma unroll
            for (int k = 0; k < 3; k++) {
                int c = threadIdx.x + k * 256;
                acc[k] += f_sem[(((size_t)b * CD + c) * HP + i) * HP + j];
            }
        }
    }
    float inv = cnt > 0 ? 1.0f / (float)cnt : 0.0f;
#pragma unroll
    for (int k = 0; k < 3; k++) {
        int c = threadIdx.x + k * 256;
        g_means[((size_t)b * NSEG + s) * CD + c] = acc[k] * inv;
    }
}

// -------- antialiased bilinear 336->48 weights per segment ------------------
__global__ void paint_wseg_k(const int* __restrict__ segmap) {
    const int X = blockIdx.x, Y = blockIdx.y, b = blockIdx.z;
    const int t = threadIdx.x;
    __shared__ float wseg[NSEG];
    __shared__ float wy[15], wx[15];

    if (t < NSEG) wseg[t] = 0.f;
    if (t == 0) {
        float sf = 7.0f * Y + 3.0f, norm = 0.f;
        for (int k = 0; k < 15; k++) {
            int y = 7 * Y - 4 + k;
            float w = (y >= 0 && y < HIMG)
                          ? fmaxf(0.f, 1.f - fabsf((float)y - sf) * (1.f / 7.f)) : 0.f;
            wy[k] = w; norm += w;
        }
        float inv = 1.f / norm;
        for (int k = 0; k < 15; k++) wy[k] *= inv;
    }
    if (t == 1) {
        float sf = 7.0f * X + 3.0f, norm = 0.f;
        for (int k = 0; k < 15; k++) {
            int x = 7 * X - 4 + k;
            float w = (x >= 0 && x < HIMG)
                          ? fmaxf(0.f, 1.f - fabsf((float)x - sf) * (1.f / 7.f)) : 0.f;
            wx[k] = w; norm += w;
        }
        float inv = 1.f / norm;
        for (int k = 0; k < 15; k++) wx[k] *= inv;
    }
    __syncthreads();

    if (t < 225) {
        int ty = t / 15, tx = t % 15;
        int y = 7 * Y - 4 + ty, x = 7 * X - 4 + tx;
        if (y >= 0 && y < HIMG && x >= 0 && x < HIMG) {
            float w = wy[ty] * wx[tx];
            if (w != 0.f) {
                int seg = segmap[((size_t)b * HIMG + y) * HIMG + x];
                seg = min(max(seg, 0), NSEG - 1);
                atomicAdd(&wseg[seg], w);
            }
        }
    }
    __syncthreads();
    if (t < NSEG)
        g_wseg[((size_t)b * NSEG + t) * P2 + Y * RH + X] = wseg[t];
}

// -------- fold means into shconv weights (K-split x4 partials) --------------
// grid (6, 128, 4), 576 threads: tap = t/64 (warp-constant), s = t%64.
__global__ void __launch_bounds__(576) fold_wm_part_k(
    const float* __restrict__ ws0, const float* __restrict__ ws1,
    const float* __restrict__ ws2) {
    __shared__ float msm[NSEG * 65];
    __shared__ float wsub[64 * 9];
    const int zz = blockIdx.x, layer = zz >> 1, b = zz & 1;
    const int co = blockIdx.y;
    const int chunk = blockIdx.z;
    const float* ws = layer == 0 ? ws0 : (layer == 1 ? ws1 : ws2);
    const int t = threadIdx.x;
    const int tap = t >> 6, s = t & 63;

    float a = 0.f;
    for (int ci0 = chunk * 192; ci0 < chunk * 192 + 192; ci0 += 64) {
        __syncthreads();
        for (int i = t; i < NSEG * 64; i += 576) {
            int ss = i >> 6, cc = i & 63;
            msm[ss * 65 + cc] = g_means[((size_t)b * NSEG + ss) * CD + ci0 + cc];
        }
        wsub[t] = ws[((size_t)co * CD + ci0 + t / 9) * 9 + (t % 9)];
        __syncthreads();
        const float* mr = msm + s * 65;
        const float* wr = wsub + tap;
#pragma unroll 8
        for (int cc = 0; cc < 64; cc++)
            a = fmaf(wr[cc * 9], mr[cc], a);
    }
    g_wmp[((size_t)(chunk * 6 + zz) * HID + co) * 576 + s * 9 + tap] = a;
}

// reduce 4 K-chunk partials -> g_wm
__global__ void wm_reduce_k() {
    const int idx = blockIdx.x * 256 + threadIdx.x;
    if (idx >= 6 * HID * 576) return;
    const int zz = idx / (HID * 576);
    const int rem = idx - zz * (HID * 576);
    float s = 0.f;
#pragma unroll
    for (int c = 0; c < 4; c++)
        s += g_wmp[(size_t)(c * 6 + zz) * (HID * 576) + rem];
    g_wm[idx] = s;
}

// ---------------- layernorm stats, float4 ----------------------------------
__global__ void ln_stats4_k(const float4* __restrict__ x, int n4PerB, int layer) {
    const int b = blockIdx.y;
    const float4* xb = x + (size_t)b * n4PerB;
    float s = 0.f, s2 = 0.f;
    for (int i = blockIdx.x * blockDim.x + threadIdx.x; i < n4PerB;
         i += gridDim.x * blockDim.x) {
        float4 v = xb[i];
        s += (v.x + v.y) + (v.z + v.w);
        s2 = fmaf(v.x, v.x, fmaf(v.y, v.y, fmaf(v.z, v.z, fmaf(v.w, v.w, s2))));
    }
#pragma unroll
    for (int o = 16; o; o >>= 1) {
        s += __shfl_down_sync(0xffffffffu, s, o);
        s2 += __shfl_down_sync(0xffffffffu, s2, o);
    }
    __shared__ float sh[32][2];
    int w = threadIdx.x >> 5, l = threadIdx.x & 31;
    if (l == 0) { sh[w][0] = s; sh[w][1] = s2; }
    __syncthreads();
    if (threadIdx.x < 32) {
        int nw = blockDim.x >> 5;
        s = (threadIdx.x < nw) ? sh[threadIdx.x][0] : 0.f;
        s2 = (threadIdx.x < nw) ? sh[threadIdx.x][1] : 0.f;
#pragma unroll
        for (int o = 16; o; o >>= 1) {
            s += __shfl_down_sync(0xffffffffu, s, o);
            s2 += __shfl_down_sync(0xffffffffu, s2, o);
        }
        if (threadIdx.x == 0) {
            atomicAdd(&g_stats[layer * 4 + b * 2 + 0], s);
            atomicAdd(&g_stats[layer * 4 + b * 2 + 1], s2);
        }
    }
}

// ---- staging helpers -------------------------------------------------------
template <int CI, int NE>
__device__ __forceinline__ void stage_pre(int* gofs, int* sofs,
                                          int ty0, int tx0, int t) {
#pragma unroll
    for (int k = 0; k < NE; k++) {
        int idx = t + k * 128;
        if (idx < CI * 324) {
            int ci = idx / 324, q = idx - ci * 324;
            int row = q / 18, col = q - row * 18;
            int y = ty0 + row - 1, x = tx0 + col - 1;
            bool vin = (unsigned)y < RH && (unsigned)x < RH;
            gofs[k] = vin ? (ci * P2 + y * RH + x) : -1;
            sofs[k] = (ci * 18 + row) * 20 + col;
        } else {
            gofs[k] = -1;
            sofs[k] = 18;
        }
    }
}

template <int CI, int NE>
__device__ __forceinline__ void stage_run(float* scp, const float* __restrict__ icb,
                                          const int* gofs, const int* sofs) {
#pragma unroll
    for (int k = 0; k < NE; k++) {
        int go = gofs[k];
        float v = (go >= 0) ? __ldg(icb + go) : 0.f;
        scp[sofs[k]] = v;
        scp[sofs[k] + (CI * 360 - 1)] = v;
        scp[sofs[k] + (2 * CI * 360 - 2)] = v;
    }
}

// ------- shared conv over 64 segment-channels + bias + relu -> g_h ----------
#define SCI 4
#define SNE 11
__global__ void __launch_bounds__(128) shconv_k(
    const float* __restrict__ bs0, const float* __restrict__ bs1,
    const float* __restrict__ bs2) {
    __shared__ __align__(16) float scp[3 * SCI * 360];
    __shared__ __align__(16) float2 wdup[SCI * 9 * 32];
    const int tile = blockIdx.x;
    const int ty0 = (tile / 3) * 16, tx0 = (tile % 3) * 16;
    const int co0 = blockIdx.y * 32;
    const int zz = blockIdx.z, layer = zz >> 1, b = zz & 1;
    const float* bias = layer == 0 ? bs0 : (layer == 1 ? bs1 : bs2);
    const float* wt = g_wm + (size_t)zz * HID * NSEG * 9;
    const float* in = g_wseg + (size_t)b * NSEG * P2;
    float* outp = g_h + (size_t)zz * HID * P2;
    const int t = threadIdx.x;
    const int co_i = t & 3, g = t >> 2, r = g >> 1, hh = g & 1;

    int gofs[SNE], sofs[SNE];
    stage_pre<SCI, SNE>(gofs, sofs, ty0, tx0, t);

    ull acc[8][4];
#pragma unroll
    for (int j = 0; j < 8; j++)
#pragma unroll
        for (int i = 0; i < 4; i++) acc[j][i] = 0ULL;

    for (int cb = 0; cb < NSEG; cb += SCI) {
        __syncthreads();
        stage_run<SCI, SNE>(scp, in + (size_t)cb * P2, gofs, sofs);
        for (int idx = t; idx < 32 * SCI * 9; idx += 128) {
            int co_l = idx / (SCI * 9), rem = idx - co_l * (SCI * 9);
            int ci = rem / 9, tap = rem - ci * 9;
            float w = wt[((size_t)(co0 + co_l) * NSEG + cb + ci) * 9 + tap];
            wdup[(ci * 9 + tap) * 32 + co_l] = make_float2(w, w);
        }
        __syncthreads();
#pragma unroll
        for (int ci = 0; ci < SCI; ci++) {
#pragma unroll
            for (int ky = 0; ky < 3; ky++) {
#pragma unroll
                for (int kx = 0; kx < 3; kx++) {
                    const ulonglong2* pp = (const ulonglong2*)(scp + kx * (SCI * 360) +
                        (ci * 18 + r + ky) * 20 + hh * 8);
                    ulonglong2 pA = pp[0], pB = pp[1];
                    const ulonglong2* wp = (const ulonglong2*)(wdup +
                        (ci * 9 + ky * 3 + kx) * 32 + co_i * 8);
                    ulonglong2 wA = wp[0], wB = wp[1], wC = wp[2], wD = wp[3];
                    FFMA2(acc[0][0], pA.x, wA.x); FFMA2(acc[0][1], pA.y, wA.x);
                    FFMA2(acc[0][2], pB.x, wA.x); FFMA2(acc[0][3], pB.y, wA.x);
                    FFMA2(acc[1][0], pA.x, wA.y); FFMA2(acc[1][1], pA.y, wA.y);
                    FFMA2(acc[1][2], pB.x, wA.y); FFMA2(acc[1][3], pB.y, wA.y);
                    FFMA2(acc[2][0], pA.x, wB.x); FFMA2(acc[2][1], pA.y, wB.x);
                    FFMA2(acc[2][2], pB.x, wB.x); FFMA2(acc[2][3], pB.y, wB.x);
                    FFMA2(acc[3][0], pA.x, wB.y); FFMA2(acc[3][1], pA.y, wB.y);
                    FFMA2(acc[3][2], pB.x, wB.y); FFMA2(acc[3][3], pB.y, wB.y);
                    FFMA2(acc[4][0], pA.x, wC.x); FFMA2(acc[4][1], pA.y, wC.x);
                    FFMA2(acc[4][2], pB.x, wC.x); FFMA2(acc[4][3], pB.y, wC.x);
                    FFMA2(acc[5][0], pA.x, wC.y); FFMA2(acc[5][1], pA.y, wC.y);
                    FFMA2(acc[5][2], pB.x, wC.y); FFMA2(acc[5][3], pB.y, wC.y);
                    FFMA2(acc[6][0], pA.x, wD.x); FFMA2(acc[6][1], pA.y, wD.x);
                    FFMA2(acc[6][2], pB.x, wD.x); FFMA2(acc[6][3], pB.y, wD.x);
                    FFMA2(acc[7][0], pA.x, wD.y); FFMA2(acc[7][1], pA.y, wD.y);
                    FFMA2(acc[7][2], pB.x, wD.y); FFMA2(acc[7][3], pB.y, wD.y);
                }
            }
        }
    }
    const int pg = (ty0 + r) * RH + tx0 + hh * 8;
#pragma unroll
    for (int j = 0; j < 8; j++) {
        int c = co0 + co_i * 8 + j;
        float bv = bias[c];
        float f[8];
#pragma unroll
        for (int i = 0; i < 4; i++) UNPK(f[2 * i], f[2 * i + 1], acc[j][i]);
        *(float4*)(outp + (size_t)c * P2 + pg) =
            make_float4(fmaxf(f[0] + bv, 0.f), fmaxf(f[1] + bv, 0.f),
                        fmaxf(f[2] + bv, 0.f), fmaxf(f[3] + bv, 0.f));
        *(float4*)(outp + (size_t)c * P2 + pg + 4) =
            make_float4(fmaxf(f[4] + bv, 0.f), fmaxf(f[5] + bv, 0.f),
                        fmaxf(f[6] + bv, 0.f), fmaxf(f[7] + bv, 0.f));
    }
}

// ------- fold beta weights --------------------------------------------------
__global__ void fold_wb_k(const float* __restrict__ w0, const float* __restrict__ wb) {
    const int k = blockIdx.x * 128 + threadIdx.x;
    const int c0 = blockIdx.y * 128;
    __shared__ float w0s[8][128];
    for (int i = threadIdx.x; i < 8 * 128; i += 128)
        w0s[i >> 7][i & 127] = w0[(size_t)(i >> 7) * CM + c0 + (i & 127)];
    __syncthreads();
    float acc[8] = {0, 0, 0, 0, 0, 0, 0, 0};
#pragma unroll 4
    for (int cc = 0; cc < 128; cc++) {
        float v = wb[(size_t)(c0 + cc) * (HID * 9) + k];
#pragma unroll
        for (int j = 0; j < 8; j++) acc[j] = fmaf(w0s[j][cc], v, acc[j]);
    }
#pragma unroll
    for (int j = 0; j < 8; j++) atomicAdd(&g_wbf[j * (HID * 9) + k], acc[j]);
}

__global__ void cb0_k(const float* __restrict__ w0, const float* __restrict__ bb) {
    const int j = blockIdx.x;
    float s = 0.f;
    for (int c = threadIdx.x; c < CM; c += 256)
        s = fmaf(w0[(size_t)j * CM + c], bb[c], s);
#pragma unroll
    for (int o = 16; o; o >>= 1) s += __shfl_down_sync(~0u, s, o);
    __shared__ float sh[8];
    if ((threadIdx.x & 31) == 0) sh[threadIdx.x >> 5] = s;
    __syncthreads();
    if (threadIdx.x == 0) {
        float r = 0.f;
        for (int w = 0; w < 8; w++) r += sh[w];
        g_cb0[j] = r;
    }
}

// ------- beta conv (channel-split x4): 32ci of h -> 8ch partials ------------
__global__ void conv_beta_k() {
    const int tile = blockIdx.x, sp = blockIdx.y, b = blockIdx.z;
    const int ty0 = (tile / 3) * 16, tx0 = (tile % 3) * 16;
    const int t = threadIdx.x;
    const int py = t >> 4, px = t & 15;
    __shared__ float sin_s[8][324];
    __shared__ float sw[8][8][9];
    float acc[8] = {0, 0, 0, 0, 0, 0, 0, 0};
    const float* hin = g_h + (size_t)b * HID * P2;
    for (int cb = sp * 32; cb < sp * 32 + 32; cb += 8) {
        for (int idx = t; idx < 8 * 324; idx += 256) {
            int c = idx / 324, q = idx - c * 324;
            int iy = ty0 + q / 18 - 1, ix = tx0 + (q % 18) - 1;
            float v = 0.f;
            if ((unsigned)iy < RH && (unsigned)ix < RH)
                v = hin[(size_t)(cb + c) * P2 + iy * RH + ix];
            sin_s[c][q] = v;
        }
        for (int idx = t; idx < 576; idx += 256) {
            int co = idx / 72, rr = idx - co * 72;
            sw[co][rr / 9][rr % 9] = g_wbf[co * (HID * 9) + (cb + rr / 9) * 9 + (rr % 9)];
        }
        __syncthreads();
#pragma unroll
        for (int ci = 0; ci < 8; ci++) {
            float v[9];
#pragma unroll
            for (int ky = 0; ky < 3; ky++)
#pragma unroll
                for (int kx = 0; kx < 3; kx++)
                    v[ky * 3 + kx] = sin_s[ci][(py + ky) * 18 + px + kx];
#pragma unroll
            for (int co = 0; co < 8; co++) {
                float a = acc[co];
#pragma unroll
                for (int k = 0; k < 9; k++) a = fmaf(v[k], sw[co][ci][k], a);
                acc[co] = a;
            }
        }
        __syncthreads();
    }
    const int p = (ty0 + py) * RH + tx0 + px;
#pragma unroll
    for (int co = 0; co < 8; co++)
        g_bpart[((sp * NB + b) * 8 + co) * P2 + p] = acc[co];
}

// ------- layer0: bf16 mma gamma conv + fused LN + 1x1 contraction -----------
__global__ void __launch_bounds__(128) spade0_k(
    const float* __restrict__ wg, const float* __restrict__ bg,
    const float* __restrict__ x, const float* __restrict__ w0) {
    __shared__ uint ppatch[8 * 360];
    __shared__ uint afrag[9 * 2 * 32 * 4];
    __shared__ float w0s[8][32], w0ps[8][32];

    const int tile = blockIdx.x;
    const int ty0 = (tile / 3) * 16, tx0 = (tile % 3) * 16;
    const int co0 = blockIdx.y * 32;
    const int b = blockIdx.z;
    const float* hin = g_h + (size_t)b * HID * P2;
    const int t = threadIdx.x;
    const int wid = t >> 5, l = t & 31, g4 = l >> 2, k4 = l & 3;

    for (int i = t; i < 256; i += 128) {
        int j8 = i >> 5, col = i & 31;
        float wv = w0[(size_t)j8 * CM + co0 + col];
        w0s[j8][col] = wv;
        w0ps[j8][col] = wv * (1.f + bg[co0 + col]);
    }

    float acc[2][8][4];
#pragma unroll
    for (int m = 0; m < 2; m++)
#pragma unroll
        for (int n = 0; n < 8; n++)
#pragma unroll
            for (int i = 0; i < 4; i++) acc[m][n][i] = 0.f;

    for (int cb = 0; cb < HID; cb += 16) {
        __syncthreads();
        for (int i = t; i < 8 * 324; i += 128) {
            int p = i / 324, q = i - p * 324;
            int ry = q / 18, rx = q - ry * 18;
            int y = ty0 + ry - 1, xx = tx0 + rx - 1;
            float v0 = 0.f, v1 = 0.f;
            if ((unsigned)y < RH && (unsigned)xx < RH) {
                size_t o = (size_t)(cb + 2 * p) * P2 + y * RH + xx;
                v0 = __ldg(hin + o);
                v1 = __ldg(hin + o + P2);
            }
            uint u; BF2(u, v0, v1);
            ppatch[p * 360 + ry * 20 + rx] = u;
        }
        for (int i = t; i < 32 * 8 * 9; i += 128) {
            int co = i / 72, rem = i - co * 72;
            int p = rem / 9, tap = rem - p * 9;
            size_t base = ((size_t)(co0 + co) * HID + cb + 2 * p) * 9 + tap;
            float v0 = wg[base], v1 = wg[base + 9];
            uint u; BF2(u, v0, v1);
            int m = co >> 4, row = co & 15;
            int lane_a = (row & 7) * 4 + (p & 3);
            int reg = (row >> 3) + 2 * (p >> 2);
            afrag[((tap * 2 + m) * 32 + lane_a) * 4 + reg] = u;
        }
        __syncthreads();
#pragma unroll
        for (int tap = 0; tap < 9; tap++) {
            const int ky = tap / 3, kx = tap - ky * 3;
            uint4 am0 = *(const uint4*)&afrag[((tap * 2 + 0) * 32 + l) * 4];
            uint4 am1 = *(const uint4*)&afrag[((tap * 2 + 1) * 32 + l) * 4];
            const uint* pb = ppatch + k4 * 360 + ky * 20 + kx;
#pragma unroll
            for (int n8 = 0; n8 < 8; n8++) {
                int y = wid * 4 + (n8 >> 1);
                int xx = (n8 & 1) * 8 + g4;
                uint b0 = pb[y * 20 + xx];
                uint b1 = pb[y * 20 + xx + 4 * 360];
                MMA16(acc[0][n8], am0, b0, b1);
                MMA16(acc[1][n8], am1, b0, b1);
            }
        }
    }

    const float sum = g_stats[b * 2 + 0], sumsq = g_stats[b * 2 + 1];
    const float invN = 1.f / ((float)CM * P2);
    const float mean = sum * invN;
    const float rstd = rsqrtf(sumsq * invN - mean * mean + LNEPS);

    float* rp = g_red + ((size_t)(b * 96 + blockIdx.y) * 8) * P2;
#pragma unroll
    for (int n8 = 0; n8 < 8; n8++) {
        const int y = wid * 4 + (n8 >> 1);
        const int xc = (n8 & 1) * 8 + k4 * 2;
        const int pix = (ty0 + y) * RH + tx0 + xc;
        float s0[8], s1[8];
#pragma unroll
        for (int j = 0; j < 8; j++) { s0[j] = 0.f; s1[j] = 0.f; }
#pragma unroll
        for (int m = 0; m < 2; m++) {
#pragma unroll
            for (int rh = 0; rh < 2; rh++) {
                int col = m * 16 + rh * 8 + g4;
                float2 xv = *(const float2*)(x + ((size_t)b * CM + co0 + col) * P2 + pix);
                float xn0 = (xv.x - mean) * rstd;
                float xn1 = (xv.y - mean) * rstd;
                float g0 = acc[m][n8][rh * 2 + 0];
                float g1 = acc[m][n8][rh * 2 + 1];
                float xg0 = xn0 * g0, xg1 = xn1 * g1;
#pragma unroll
                for (int j = 0; j < 8; j++) {
                    s0[j] = fmaf(xg0, w0s[j][col], fmaf(xn0, w0ps[j][col], s0[j]));
                    s1[j] = fmaf(xg1, w0s[j][col], fmaf(xn1, w0ps[j][col], s1[j]));
                }
            }
        }
#pragma unroll
        for (int j = 0; j < 8; j++) {
            float a0 = s0[j], a1 = s1[j];
            a0 += __shfl_xor_sync(~0u, a0, 4);
            a0 += __shfl_xor_sync(~0u, a0, 8);
            a0 += __shfl_xor_sync(~0u, a0, 16);
            a1 += __shfl_xor_sync(~0u, a1, 4);
            a1 += __shfl_xor_sync(~0u, a1, 8);
            a1 += __shfl_xor_sync(~0u, a1, 16);
            if (g4 == 0) {
                rp[(size_t)j * P2 + pix] = a0;
                rp[(size_t)j * P2 + pix + 1] = a1;
            }
        }
    }
}

__device__ __forceinline__ float softplus_f(float z) {
    return fmaxf(z, 0.f) + log1pf(expf(-fabsf(z)));
}

// reduce spade0 partials + beta(4 slabs) + consts -> x1
__global__ void reduce_x1_k(const float* __restrict__ bias0) {
    const int idx = blockIdx.x * 256 + threadIdx.x;
    const int b = idx / (8 * P2);
    const int rem = idx - b * (8 * P2);
    const int j = rem / P2, p = rem - j * P2;
    const int bo = (b * 8 + j) * P2 + p;
    float s = g_cb0[j] + bias0[j];
#pragma unroll
    for (int sp = 0; sp < 4; sp++) s += g_bpart[sp * NB * 8 * P2 + bo];
    const float* base = g_red + ((size_t)b * 96 * 8 + j) * P2 + p;
#pragma unroll 8
    for (int k = 0; k < 96; k++) s += base[(size_t)k * 8 * P2];
    g_x1[idx] = softplus_f(s);
}

// ------- small spade partials (layers 1/2, channel-split x4) ----------------
__global__ void spade_part_k(const float* __restrict__ hin,
                             const float* __restrict__ wg,
                             const float* __restrict__ wb, int ch_off) {
    const int tile = blockIdx.x;
    const int ty0 = (tile / 3) * 16, tx0 = (tile % 3) * 16;
    const int co_g = blockIdx.y >> 2, sp = blockIdx.y & 3;
    const int co0 = co_g * 8;
    const int b = blockIdx.z;
    const int t = threadIdx.x;
    const int py = t >> 4, px = t & 15;

    __shared__ float sin_s[8][324];
    __shared__ float swg[8][8][9];
    __shared__ float swb[8][8][9];

    float accg[8], accb[8];
#pragma unroll
    for (int i = 0; i < 8; i++) { accg[i] = 0.f; accb[i] = 0.f; }

    const size_t inB = (size_t)b * HID * P2;
    for (int cb = sp * 32; cb < sp * 32 + 32; cb += 8) {
        for (int idx = t; idx < 8 * 324; idx += 256) {
            int c = idx / 324, q = idx - c * 324;
            int iy = ty0 + q / 18 - 1, ix = tx0 + (q % 18) - 1;
            float v = 0.f;
            if ((unsigned)iy < RH && (unsigned)ix < RH)
                v = hin[inB + (size_t)(cb + c) * P2 + iy * RH + ix];
            sin_s[c][q] = v;
        }
        for (int idx = t; idx < 576; idx += 256) {
            int co = idx / 72, rr = idx - co * 72;
            size_t wi = ((size_t)(co0 + co) * HID + cb + rr / 9) * 9 + (rr % 9);
            swg[co][rr / 9][rr % 9] = wg[wi];
            swb[co][rr / 9][rr % 9] = wb[wi];
        }
        __syncthreads();
#pragma unroll
        for (int ci = 0; ci < 8; ci++) {
            float v[9];
#pragma unroll
            for (int ky = 0; ky < 3; ky++)
#pragma unroll
                for (int kx = 0; kx < 3; kx++)
                    v[ky * 3 + kx] = sin_s[ci][(py + ky) * 18 + px + kx];
#pragma unroll
            for (int co = 0; co < 8; co++) {
                float agv = accg[co], abv = accb[co];
#pragma unroll
                for (int k = 0; k < 9; k++) {
                    agv = fmaf(v[k], swg[co][ci][k], agv);
                    abv = fmaf(v[k], swb[co][ci][k], abv);
                }
                accg[co] = agv; accb[co] = abv;
            }
        }
        __syncthreads();
    }

    const int p = (ty0 + py) * RH + tx0 + px;
#pragma unroll
    for (int co = 0; co < 8; co++) {
        int ch = ch_off + co0 + co;
        g_sgp[((sp * NB + b) * 24 + ch) * P2 + p] = accg[co];
        g_sbp[((sp * NB + b) * 24 + ch) * P2 + p] = accb[co];
    }
}

// merge partials + LN apply -> act
__global__ void merge_small_k(const float* __restrict__ x,
                              const float* __restrict__ bg,
                              const float* __restrict__ bb,
                              float* __restrict__ act,
                              int layer, int nf, int ch_off, float invN) {
    const int idx = blockIdx.x * 256 + threadIdx.x;
    if (idx >= NB * nf * P2) return;
    const int b = idx / (nf * P2);
    const int rem = idx - b * (nf * P2);
    const int c = rem / P2, p = rem - c * P2;
    float gv = 0.f, bv = 0.f;
#pragma unroll
    for (int sp = 0; sp < 4; sp++) {
        int o = ((sp * NB + b) * 24 + ch_off + c) * P2 + p;
        gv += g_sgp[o];
        bv += g_sbp[o];
    }
    const float sum = g_stats[layer * 4 + b * 2 + 0];
    const float sumsq = g_stats[layer * 4 + b * 2 + 1];
    const float mean = sum * invN;
    const float rstd = rsqrtf(sumsq * invN - mean * mean + LNEPS);
    float xv = x[idx];
    act[idx] = fmaf((xv - mean) * rstd, 1.f + gv + bg[c], bv + bb[c]);
}

template <int COUT>
__global__ void conv1x1_softplus_k(const float* __restrict__ act,
                                   const float* __restrict__ w,
                                   const float* __restrict__ bias,
                                   float* __restrict__ out, int Cin) {
    const int p = blockIdx.x * blockDim.x + threadIdx.x;
    const int b = blockIdx.y;
    float acc[COUT];
#pragma unroll
    for (int j = 0; j < COUT; j++) acc[j] = 0.f;
    const float* ab = act + (size_t)b * Cin * P2 + p;
#pragma unroll 4
    for (int c = 0; c < Cin; c++) {
        float v = ab[(size_t)c * P2];
#pragma unroll
        for (int j = 0; j < COUT; j++)
            acc[j] = fmaf(__ldg(&w[(size_t)j * Cin + c]), v, acc[j]);
    }
#pragma unroll
    for (int j = 0; j < COUT; j++)
        out[((size_t)b * COUT + j) * P2 + p] = softplus_f(acc[j] + bias[j]);
}

// ---------------------------------------------------------------------------
static float* sym_ptr(const void* sym) {
    void* p = nullptr;
    cudaGetSymbolAddress(&p, sym);
    return (float*)p;
}

extern "C" void kernel_launch(void* const* d_in, const int* in_sizes, int n_in,
                              void* d_out, int out_size) {
    const float* x_main = (const float*)d_in[0];
    const float* f_sem = (const float*)d_in[1];
    const int* segmap = (const int*)d_in[2];
    const float* ws[3] = {(const float*)d_in[3], (const float*)d_in[9], (const float*)d_in[15]};
    const float* bs[3] = {(const float*)d_in[4], (const float*)d_in[10], (const float*)d_in[16]};
    const float* wg[3] = {(const float*)d_in[5], (const float*)d_in[11], (const float*)d_in[17]};
    const float* bg[3] = {(const float*)d_in[6], (const float*)d_in[12], (const float*)d_in[18]};
    const float* wb[3] = {(const float*)d_in[7], (const float*)d_in[13], (const float*)d_in[19]};
    const float* bb[3] = {(const float*)d_in[8], (const float*)d_in[14], (const float*)d_in[20]};
    const float* w1x[3] = {(const float*)d_in[21], (const float*)d_in[23], (const float*)d_in[25]};
    const float* b1x[3] = {(const float*)d_in[22], (const float*)d_in[24], (const float*)d_in[26]};
    float* out = (float*)d_out;

    float* p_h = sym_ptr(g_h);
    float* p_x1 = sym_ptr(g_x1);
    float* p_act1 = sym_ptr(g_act1);
    float* p_x2 = sym_ptr(g_x2);
    float* p_act2 = sym_ptr(g_act2);

    zero_k<<<36, 256>>>();
    seg_means_k<<<dim3(NSEG, NB), 256>>>(f_sem, segmap);
    paint_wseg_k<<<dim3(RH, RH, NB), 256>>>(segmap);
    fold_wm_part_k<<<dim3(6, HID, 4), 576>>>(ws[0], ws[1], ws[2]);
    wm_reduce_k<<<(6 * HID * 576 + 255) / 256, 256>>>();
    fold_wb_k<<<dim3(9, 24), 128>>>(w1x[0], wb[0]);
    cb0_k<<<8, 256>>>(w1x[0], bb[0]);
    ln_stats4_k<<<dim3(512, NB), 256>>>((const float4*)x_main, CM * P2 / 4, 0);

    shconv_k<<<dim3(9, HID / 32, 6), 128>>>(bs[0], bs[1], bs[2]);
    conv_beta_k<<<dim3(9, 4, NB), 256>>>();

    spade_part_k<<<dim3(9, 4, NB), 256>>>(p_h + (size_t)1 * NB * HID * P2,
                                          wg[1], wb[1], 0);
    spade_part_k<<<dim3(9, 8, NB), 256>>>(p_h + (size_t)2 * NB * HID * P2,
                                          wg[2], wb[2], 8);

    // ---- layer 0 ----
    spade0_k<<<dim3(9, CM / 32, NB), 128>>>(wg[0], bg[0], x_main, w1x[0]);
    reduce_x1_k<<<(NB * 8 * P2) / 256, 256>>>(b1x[0]);

    // ---- layer 1 ----
    ln_stats4_k<<<dim3(2, NB), 256>>>((const float4*)p_x1, 8 * P2 / 4, 1);
    merge_small_k<<<(NB * 8 * P2 + 255) / 256, 256>>>(p_x1, bg[1], bb[1], p_act1,
                                                      1, 8, 0, 1.f / (8 * P2));
    conv1x1_softplus_k<16><<<dim3(9, NB), 256>>>(p_act1, w1x[1], b1x[1], p_x2, 8);

    // ---- layer 2 ----
    ln_stats4_k<<<dim3(2, NB), 256>>>((const float4*)p_x2, 16 * P2 / 4, 2);
    merge_small_k<<<(NB * 16 * P2 + 255) / 256, 256>>>(p_x2, bg[2], bb[2], p_act2,
                                                       2, 16, 8, 1.f / (16 * P2));
    conv1x1_softplus_k<1><<<dim3(9, NB), 256>>>(p_act2, w1x[2], b1x[2], out, 16);
}